// round 7
// baseline (speedup 1.0000x reference)
#include <cuda_runtime.h>

// ---------------------------------------------------------------------------
// B=512, NQ=10, NA=4, T=16, DEG=4, LAYERS=2, F=64, NROTS=80, QFF_NROTS=40
// State: q = i>>4 (10-bit query), t = i&15 (ancilla). Warp w owns t=w.
// In-warp: 1024 amps, 32 f32x2 regs/lane. Alternating qubit map:
//   qubit Q even -> register bit Q/2 ; qubit Q odd -> lane bit Q/2.
// Fusion: each reg-ctrl/lane-tgt crx (even ctrl) is fused with the commuting
// lane-ry on its target qubit (hoisted adjacent; legality checked per pair).
// ---------------------------------------------------------------------------

#define BATCH 512

typedef unsigned long long f2x;

__device__ float2 g_cs[BATCH * 1280];   // (cos,sin) half-angles per (b,t,gate)
__device__ ulonglong2 g_Mpk[3 * 256];   // packed mix matrices {(m.x,m.x),(m.y,m.y)}
__device__ float2 g_qffcs[40];
__device__ float2 g_v0[16];

// ---- f32x2 primitives ------------------------------------------------------
static __device__ __forceinline__ f2x f2pack(float lo, float hi) {
    f2x r; asm("mov.b64 %0, {%1, %2};" : "=l"(r) : "f"(lo), "f"(hi)); return r;
}
static __device__ __forceinline__ void f2unpack(f2x v, float& lo, float& hi) {
    asm("mov.b64 {%0, %1}, %2;" : "=f"(lo), "=f"(hi) : "l"(v));
}
static __device__ __forceinline__ f2x f2fma(f2x a, f2x b, f2x c) {
    f2x r; asm("fma.rn.f32x2 %0, %1, %2, %3;" : "=l"(r) : "l"(a), "l"(b), "l"(c)); return r;
}
static __device__ __forceinline__ f2x f2mul(f2x a, f2x b) {
    f2x r; asm("mul.rn.f32x2 %0, %1, %2;" : "=l"(r) : "l"(a), "l"(b)); return r;
}
static __device__ __forceinline__ f2x f2swap(f2x v) {
    float lo, hi; f2unpack(v, lo, hi); return f2pack(hi, lo);
}
static __device__ __forceinline__ f2x f2iswap(f2x v) {  // i * (x + iy) = (-y, x)
    float lo, hi; f2unpack(v, lo, hi); return f2pack(-hi, lo);
}
static __device__ __forceinline__ f2x f2shfl(f2x v, int m) {
    float lo, hi; f2unpack(v, lo, hi);
    lo = __shfl_xor_sync(0xffffffffu, lo, m);
    hi = __shfl_xor_sync(0xffffffffu, hi, m);
    return f2pack(lo, hi);
}
static __device__ __forceinline__ f2x f2shflswap(f2x v, int m) {
    float lo, hi; f2unpack(v, lo, hi);
    lo = __shfl_xor_sync(0xffffffffu, lo, m);
    hi = __shfl_xor_sync(0xffffffffu, hi, m);
    return f2pack(hi, lo);
}
static __device__ __forceinline__ float2 cmulf(float2 a, float2 b) {
    return make_float2(a.x * b.x - a.y * b.y, a.x * b.y + a.y * b.x);
}

// ---- gates -----------------------------------------------------------------
template <int Q>
static __device__ __forceinline__ void ry_g(f2x* s, f2x cc, f2x sp, f2x ns, int lane) {
    if constexpr ((Q & 1) == 0) {
        constexpr int M = 1 << (Q / 2);
#pragma unroll
        for (int r = 0; r < 32; ++r)
            if (!(r & M)) {
                f2x a = s[r], b = s[r | M];
                s[r]     = f2fma(cc, a, f2mul(ns, b));
                s[r | M] = f2fma(cc, b, f2mul(sp, a));
            }
    } else {
        constexpr int L = 1 << (Q / 2);
        const f2x t = (lane & L) ? sp : ns;
#pragma unroll
        for (int r = 0; r < 32; ++r) {
            f2x o = f2shfl(s[r], L);
            s[r] = f2fma(cc, s[r], f2mul(t, o));
        }
    }
}

// crx (ctrl=1): new = c*own + sn*(other.y, -other.x); pk = (sn, -sn).
template <int C, int TQ>
static __device__ __forceinline__ void crx_g(f2x* s, f2x cc, f2x pk, int lane) {
    if constexpr ((C & 1) == 0 && (TQ & 1) == 1) {        // reg ctrl, lane tgt
        constexpr int MC = 1 << (C / 2), LT = 1 << (TQ / 2);
#pragma unroll
        for (int r = 0; r < 32; ++r)
            if (r & MC) {
                f2x osw = f2shflswap(s[r], LT);
                s[r] = f2fma(cc, s[r], f2mul(pk, osw));
            }
    } else {                                              // lane ctrl, reg tgt: no shfl
        constexpr int LC = 1 << (C / 2), MT = 1 << (TQ / 2);
        const bool act = (lane & LC) != 0;
        const f2x cc2 = act ? cc : f2pack(1.f, 1.f);
        const f2x pk2 = act ? pk : 0ull;
#pragma unroll
        for (int r = 0; r < 32; ++r)
            if (!(r & MT)) {
                f2x a = s[r], b = s[r | MT];
                s[r]      = f2fma(cc2, a, f2mul(pk2, f2swap(b)));
                s[r | MT] = f2fma(cc2, b, f2mul(pk2, f2swap(a)));
            }
    }
}

// Fused op on (reg qubit C even, lane qubit T odd):
//   fwd (QS=false): RY_T(phi) * CRX_{C,T}(theta)   [crx first, ry second]
//   adj (QS=true, caller passes negated sines): CRX(-th) * RY(-ph) == same
//   formulas with Q -> -Q (derived: diagonal imag flips, off-diag identical).
// c-bit=0 regs: plain ry. c-bit=1 regs: complex 2x2
//   lo: out = (P+iQ)*own + (-R-iS)*partner ; hi: out = (P-iQ)*own + (R-iS)*partner
template <int C, int T, bool QS>
static __device__ __forceinline__ void fuse_g(f2x* s, float cth, float sth,
                                              float cph, float sph, int lane) {
    constexpr int MC = 1 << (C / 2), LT = 1 << (T / 2);
    float P = cph * cth, Q = sph * sth, R = sph * cth, S = cph * sth;
    if (QS) Q = -Q;
    const bool hi = (lane & LT) != 0;
    const f2x cP   = f2pack(P, P);
    const f2x cAim = hi ? f2pack(-Q, -Q) : f2pack(Q, Q);
    const f2x cBre = hi ? f2pack(R, R) : f2pack(-R, -R);
    const f2x cBim = f2pack(-S, -S);
    const f2x cc   = f2pack(cph, cph);
    const f2x tp   = hi ? f2pack(sph, sph) : f2pack(-sph, -sph);
#pragma unroll
    for (int r = 0; r < 32; ++r) {
        f2x p = f2shfl(s[r], LT);
        if ((r & MC) == 0) {
            s[r] = f2fma(cc, s[r], f2mul(tp, p));
        } else {
            f2x ia = f2iswap(s[r]);
            f2x ip = f2iswap(p);
            s[r] = f2fma(cP, s[r], f2fma(cAim, ia, f2fma(cBre, p, f2mul(cBim, ip))));
        }
    }
}

// ---- gate list macros ------------------------------------------------------
#define RYF(Q, I)  { float2 g = cs[I]; f2x cc = f2pack(g.x, g.x), sp = f2pack(g.y, g.y), \
                     ns = f2pack(-g.y, -g.y); ry_g<Q>(s, cc, sp, ns, lane); }
#define RYA(Q, I)  { float2 g = cs[I]; f2x cc = f2pack(g.x, g.x), sp = f2pack(-g.y, -g.y), \
                     ns = f2pack(g.y, g.y); ry_g<Q>(s, cc, sp, ns, lane); }
#define CRXF(C, T, I) { float2 g = cs[I]; f2x cc = f2pack(g.x, g.x), pk = f2pack(g.y, -g.y); \
                        crx_g<C, T>(s, cc, pk, lane); }
#define CRXA(C, T, I) { float2 g = cs[I]; f2x cc = f2pack(g.x, g.x), pk = f2pack(-g.y, g.y); \
                        crx_g<C, T>(s, cc, pk, lane); }
#define FUSF(C, T, I, J) { float2 g1 = cs[I], g2 = cs[J]; \
                           fuse_g<C, T, false>(s, g1.x, g1.y, g2.x, g2.y, lane); }
#define FUSA(C, T, I, J) { float2 g1 = cs[I], g2 = cs[J]; \
                           fuse_g<C, T, true>(s, g1.x, -g1.y, g2.x, -g2.y, lane); }

// Forward 2-layer select, after block1-L1 (ry@0..9). Reordered-with-fusion:
// ring1-L1 fused with block2-L1 lane-rys; ring2-L1 fused with block1-L2
// lane-rys; ring1-L2 fused with block2-L2 lane-rys; ring2-L2 plain.
#define SELECT_FWD_TAIL()                                                       \
    CRXF(9, 0, 10) FUSF(8, 9, 11, 29) CRXF(7, 8, 12) FUSF(6, 7, 13, 27)         \
    CRXF(5, 6, 14) FUSF(4, 5, 15, 25) CRXF(3, 4, 16) FUSF(2, 3, 17, 23)         \
    CRXF(1, 2, 18) FUSF(0, 1, 19, 21)                                           \
    RYF(0, 20) RYF(2, 22) RYF(4, 24) RYF(6, 26) RYF(8, 28)                      \
    CRXF(9, 8, 30) FUSF(0, 9, 31, 49) CRXF(1, 0, 32) FUSF(2, 1, 33, 41)         \
    CRXF(3, 2, 34) FUSF(4, 3, 35, 43) CRXF(5, 4, 36) FUSF(6, 5, 37, 45)         \
    CRXF(7, 6, 38) FUSF(8, 7, 39, 47)                                           \
    RYF(0, 40) RYF(2, 42) RYF(4, 44) RYF(6, 46) RYF(8, 48)                      \
    CRXF(9, 0, 50) FUSF(8, 9, 51, 69) CRXF(7, 8, 52) FUSF(6, 7, 53, 67)         \
    CRXF(5, 6, 54) FUSF(4, 5, 55, 65) CRXF(3, 4, 56) FUSF(2, 3, 57, 63)         \
    CRXF(1, 2, 58) FUSF(0, 1, 59, 61)                                           \
    RYF(0, 60) RYF(2, 62) RYF(4, 64) RYF(6, 66) RYF(8, 68)                      \
    CRXF(9, 8, 70) CRXF(0, 9, 71) CRXF(1, 0, 72) CRXF(2, 1, 73) CRXF(3, 2, 74)  \
    CRXF(4, 3, 75) CRXF(5, 4, 76) CRXF(6, 5, 77) CRXF(7, 6, 78) CRXF(8, 7, 79)

// Adjoint select: exact reverse of [block1-L1 + SELECT_FWD_TAIL], adjointed.
#define SELECT_ADJ()                                                            \
    CRXA(8, 7, 79) CRXA(7, 6, 78) CRXA(6, 5, 77) CRXA(5, 4, 76) CRXA(4, 3, 75)  \
    CRXA(3, 2, 74) CRXA(2, 1, 73) CRXA(1, 0, 72) CRXA(0, 9, 71) CRXA(9, 8, 70)  \
    RYA(8, 68) RYA(6, 66) RYA(4, 64) RYA(2, 62) RYA(0, 60)                      \
    FUSA(0, 1, 59, 61) CRXA(1, 2, 58) FUSA(2, 3, 57, 63) CRXA(3, 4, 56)         \
    FUSA(4, 5, 55, 65) CRXA(5, 6, 54) FUSA(6, 7, 53, 67) CRXA(7, 8, 52)         \
    FUSA(8, 9, 51, 69) CRXA(9, 0, 50)                                           \
    RYA(8, 48) RYA(6, 46) RYA(4, 44) RYA(2, 42) RYA(0, 40)                      \
    FUSA(8, 7, 39, 47) CRXA(7, 6, 38) FUSA(6, 5, 37, 45) CRXA(5, 4, 36)         \
    FUSA(4, 3, 35, 43) CRXA(3, 2, 34) FUSA(2, 1, 33, 41) CRXA(1, 0, 32)         \
    FUSA(0, 9, 31, 49) CRXA(9, 8, 30)                                           \
    RYA(8, 28) RYA(6, 26) RYA(4, 24) RYA(2, 22) RYA(0, 20)                      \
    FUSA(0, 1, 19, 21) CRXA(1, 2, 18) FUSA(2, 3, 17, 23) CRXA(3, 4, 16)         \
    FUSA(4, 5, 15, 25) CRXA(5, 6, 14) FUSA(6, 7, 13, 27) CRXA(7, 8, 12)         \
    FUSA(8, 9, 11, 29) CRXA(9, 0, 10)                                           \
    RYA(9, 9) RYA(8, 8) RYA(7, 7) RYA(6, 6) RYA(5, 5)                           \
    RYA(4, 4) RYA(3, 3) RYA(2, 2) RYA(1, 1) RYA(0, 0)

// Single qff layer (fwd), ring1 fused with block2 lane-rys, ring2 plain.
#define QFF_LAYER()                                                             \
    RYF(0, 0) RYF(1, 1) RYF(2, 2) RYF(3, 3) RYF(4, 4)                           \
    RYF(5, 5) RYF(6, 6) RYF(7, 7) RYF(8, 8) RYF(9, 9)                           \
    CRXF(9, 0, 10) FUSF(8, 9, 11, 29) CRXF(7, 8, 12) FUSF(6, 7, 13, 27)         \
    CRXF(5, 6, 14) FUSF(4, 5, 15, 25) CRXF(3, 4, 16) FUSF(2, 3, 17, 23)         \
    CRXF(1, 2, 18) FUSF(0, 1, 19, 21)                                           \
    RYF(0, 20) RYF(2, 22) RYF(4, 24) RYF(6, 26) RYF(8, 28)                      \
    CRXF(9, 8, 30) CRXF(0, 9, 31) CRXF(1, 0, 32) CRXF(2, 1, 33) CRXF(3, 2, 34)  \
    CRXF(4, 3, 35) CRXF(5, 4, 36) CRXF(6, 5, 37) CRXF(7, 6, 38) CRXF(8, 7, 39)

static __device__ __forceinline__ void run_select_fwd_tail(f2x* s, const float2* cs, int lane) {
    SELECT_FWD_TAIL()
}
static __device__ __forceinline__ void run_select_fwd_full(f2x* s, const float2* cs, int lane) {
    RYF(0, 0) RYF(1, 1) RYF(2, 2) RYF(3, 3) RYF(4, 4)
    RYF(5, 5) RYF(6, 6) RYF(7, 7) RYF(8, 8) RYF(9, 9)
    SELECT_FWD_TAIL()
}
static __device__ __forceinline__ void run_select_adj(f2x* s, const float2* cs, int lane) {
    SELECT_ADJ()
}
static __device__ __forceinline__ void run_qff(f2x* s, const float2* cs, int lane) {
    QFF_LAYER()
}

// ---- expectation values ----------------------------------------------------
template <int Q>
static __device__ __forceinline__ void expval_q(const f2x* s, int lane, float* acc) {
    float ax = 0.f, ay = 0.f, z = 0.f;
    if constexpr ((Q & 1) == 0) {
        constexpr int M = 1 << (Q / 2);
#pragma unroll
        for (int r = 0; r < 32; ++r)
            if (!(r & M)) {
                float axr, ayr, bxr, byr;
                f2unpack(s[r], axr, ayr);
                f2unpack(s[r | M], bxr, byr);
                ax = fmaf(axr, bxr, fmaf(ayr, byr, ax));
                ay = fmaf(axr, byr, fmaf(-ayr, bxr, ay));
                z  = fmaf(axr, axr, fmaf(ayr, ayr, fmaf(-bxr, bxr, fmaf(-byr, byr, z))));
            }
    } else {
        constexpr int L = 1 << (Q / 2);
        const bool lo = (lane & L) == 0;
#pragma unroll
        for (int r = 0; r < 32; ++r) {
            float x, y;
            f2unpack(s[r], x, y);
            float ox = __shfl_xor_sync(0xffffffffu, x, L);
            float oy = __shfl_xor_sync(0xffffffffu, y, L);
            float n = fmaf(x, x, y * y);
            if (lo) {
                ax = fmaf(x, ox, fmaf(y, oy, ax));
                ay = fmaf(x, oy, fmaf(-y, ox, ay));
                z += n;
            } else {
                z -= n;
            }
        }
    }
#pragma unroll
    for (int off = 16; off; off >>= 1) {
        ax += __shfl_xor_sync(0xffffffffu, ax, off);
        ay += __shfl_xor_sync(0xffffffffu, ay, off);
        z  += __shfl_xor_sync(0xffffffffu, z, off);
    }
    if (lane == 0) {
        atomicAdd(&acc[Q], 2.f * ax);
        atomicAdd(&acc[10 + Q], 2.f * ay);
        atomicAdd(&acc[20 + Q], z);
    }
}

// ---------------------------------------------------------------------------
// Projection kernel (circuit-constant setup fused into block 0)
// ---------------------------------------------------------------------------
__global__ void qts_proj(const float* __restrict__ x, const float* __restrict__ Wp,
                         const float* __restrict__ bp, const float* __restrict__ prep,
                         const float* __restrict__ sig, const float* __restrict__ qff) {
    __shared__ float xe[16][64];
    __shared__ float WsT[64][80];
    __shared__ float2 U[16][16];
    int b = blockIdx.x, tid = threadIdx.x;

    if (b == 0) {
        if (tid < 16) {
            float2 v[16];
            for (int t = 0; t < 16; ++t) v[t] = make_float2(t == tid ? 1.f : 0.f, 0.f);
            for (int ly = 0; ly < 4; ++ly) {
                for (int qi = 0; qi < 4; ++qi) {
                    int m = 1 << (3 - qi);
                    float th = prep[(ly * 4 + qi) * 2 + 0];
                    float c, sn;
                    sincosf(0.5f * th, &sn, &c);
                    for (int j = 0; j < 16; ++j)
                        if (!(j & m)) {
                            float2 a0 = v[j], a1 = v[j | m];
                            v[j]     = make_float2(c * a0.x - sn * a1.x, c * a0.y - sn * a1.y);
                            v[j | m] = make_float2(sn * a0.x + c * a1.x, sn * a0.y + c * a1.y);
                        }
                    th = prep[(ly * 4 + qi) * 2 + 1];
                    sincosf(0.5f * th, &sn, &c);
                    float2 e0 = make_float2(c, -sn), e1 = make_float2(c, sn);
                    for (int j = 0; j < 16; ++j) v[j] = cmulf(v[j], (j & m) ? e1 : e0);
                }
                for (int i = 0; i < 3; ++i) {
                    int cm = 1 << (3 - i), tm = 1 << (2 - i);
                    for (int j = 0; j < 16; ++j)
                        if ((j & cm) && !(j & tm)) {
                            float2 tmp = v[j]; v[j] = v[j | tm]; v[j | tm] = tmp;
                        }
                }
            }
            for (int t = 0; t < 16; ++t) U[t][tid] = v[t];
        }
        __syncthreads();
        if (tid < 16) {
            float c, sn;
            sincosf(sig[0], &sn, &c);
            g_v0[tid] = cmulf(make_float2(c, sn), U[tid][0]);
        }
        if (tid < 40) {
            float c, sn;
            sincosf(0.5f * qff[tid], &sn, &c);
            g_qffcs[tid] = make_float2(c, sn);
        }
        {
            int tp = tid >> 4, t = tid & 15;
            for (int m = 0; m < 3; ++m) {
                float c, sn;
                sincosf(sig[m + 1], &sn, &c);
                float2 acc = make_float2(0.f, 0.f);
                for (int si = 0; si < 16; ++si) {
                    float2 P = (si == 0) ? make_float2(c, sn) : make_float2(c, -sn);
                    float2 u = U[tp][si];
                    float2 uc = make_float2(U[t][si].x, -U[t][si].y);
                    float2 p = cmulf(cmulf(u, P), uc);
                    acc.x += p.x; acc.y += p.y;
                }
                g_Mpk[m * 256 + tp * 16 + t] =
                    make_ulonglong2(f2pack(acc.x, acc.x), f2pack(acc.y, acc.y));
            }
        }
        __syncthreads();
    }

    for (int i = tid; i < 80 * 64; i += 256) {
        int j = i / 64, f = i % 64;
        WsT[f][j] = Wp[i];
    }
    const float kdiv = -0.14391156831212787f;  // -ln(10000)/64
    for (int i = tid; i < 1024; i += 256) {
        int f = i >> 4, t = i & 15;
        float arg = (float)t * expf(kdiv * (float)(f & ~1));
        float pe = (f & 1) ? cosf(arg) : sinf(arg);
        xe[t][f] = x[b * 1024 + i] + pe;
    }
    __syncthreads();

    for (int o = tid; o < 1280; o += 256) {
        int t = o / 80, j = o % 80;
        float h = bp[j];
#pragma unroll 16
        for (int f = 0; f < 64; ++f) h = fmaf(xe[t][f], WsT[f][j], h);
        float half = 3.14159265358979323846f / (1.0f + expf(-h));
        float c, sn;
        sincosf(half, &sn, &c);
        g_cs[b * 1280 + o] = make_float2(c, sn);
    }
}

// ---------------------------------------------------------------------------
// Main kernel
// ---------------------------------------------------------------------------
static __device__ __forceinline__ void ancilla_mix(f2x* s, f2x* buf, const ulonglong2* Mk,
                                                   int w, int lane) {
#pragma unroll
    for (int r = 0; r < 32; ++r) buf[w * 1024 + r * 32 + lane] = s[r];
    __syncthreads();
#pragma unroll 1
    for (int half = 0; half < 2; ++half) {
        int q = w * 64 + half * 32 + lane;
        f2x in[16], insw[16];
#pragma unroll
        for (int t = 0; t < 16; ++t) {
            in[t] = buf[t * 1024 + q];
            float ix, iy;
            f2unpack(in[t], ix, iy);
            insw[t] = f2pack(-iy, ix);
        }
#pragma unroll
        for (int tp = 0; tp < 16; ++tp) {
            f2x a = 0ull;
#pragma unroll
            for (int t = 0; t < 16; ++t) {
                ulonglong2 m = Mk[tp * 16 + t];
                a = f2fma(m.x, in[t], a);
                a = f2fma(m.y, insw[t], a);
            }
            buf[tp * 1024 + q] = a;
        }
    }
    __syncthreads();
#pragma unroll
    for (int r = 0; r < 32; ++r) s[r] = buf[w * 1024 + r * 32 + lane];
}

__global__ __launch_bounds__(512, 1) void qts_main(const float* __restrict__ Wout,
                                                   const float* __restrict__ bout,
                                                   float* __restrict__ out) {
    extern __shared__ char smem_raw[];
    f2x* buf         = (f2x*)smem_raw;                       // [16][1024]
    ulonglong2* sMpk = (ulonglong2*)(smem_raw + 131072);     // [3][256]
    float2* sa       = (float2*)(smem_raw + 131072 + 12288); // [16][80]
    float2* sqff     = sa + 1280;                            // [40]
    float2* sv0      = sqff + 40;                            // [16]
    float* acc       = (float*)(sv0 + 16);                   // [32]

    const int tid = threadIdx.x, b = blockIdx.x;
    const int w = tid >> 5, lane = tid & 31;

    for (int i = tid; i < 1280; i += 512) sa[i] = g_cs[b * 1280 + i];
    for (int i = tid; i < 768; i += 512) sMpk[i] = g_Mpk[i];
    if (tid < 40) sqff[tid] = g_qffcs[tid];
    if (tid < 16) sv0[tid] = g_v0[tid];
    if (tid < 30) acc[tid] = 0.f;
    __syncthreads();

    const float2* cs = sa + w * 80;
    f2x s[32];

    // select k=0: first ry block on |0..0> is an exact product state (peel)
    {
        float lp = 1.f;
#pragma unroll
        for (int j = 0; j < 5; ++j) {
            float2 g = cs[2 * j + 1];
            lp *= ((lane >> j) & 1) ? g.y : g.x;
        }
        float rp[32];
        rp[0] = lp;
#pragma unroll
        for (int j = 0; j < 5; ++j) {
            float2 g = cs[2 * j];
            int m = 1 << j;
#pragma unroll
            for (int r = 0; r < 32; ++r)
                if (r < m) {
                    rp[r | m] = rp[r] * g.y;
                    rp[r]     = rp[r] * g.x;
                }
        }
        float2 v = sv0[w];
#pragma unroll
        for (int r = 0; r < 32; ++r) s[r] = f2pack(v.x * rp[r], v.y * rp[r]);

        run_select_fwd_tail(s, cs, lane);
    }
    ancilla_mix(s, buf, sMpk + 0 * 256, w, lane);

#pragma unroll 1
    for (int k = 1; k < 4; ++k) {
        if (k == 2) run_select_fwd_full(s, cs, lane);
        else        run_select_adj(s, cs, lane);
        if (k < 3) ancilla_mix(s, buf, sMpk + k * 256, w, lane);
    }

    run_qff(s, sqff, lane);

    expval_q<0>(s, lane, acc);
    expval_q<1>(s, lane, acc);
    expval_q<2>(s, lane, acc);
    expval_q<3>(s, lane, acc);
    expval_q<4>(s, lane, acc);
    expval_q<5>(s, lane, acc);
    expval_q<6>(s, lane, acc);
    expval_q<7>(s, lane, acc);
    expval_q<8>(s, lane, acc);
    expval_q<9>(s, lane, acc);
    __syncthreads();

    if (tid == 0) {
        float o = bout[0];
#pragma unroll
        for (int i = 0; i < 30; ++i) o = fmaf(acc[i], Wout[i], o);
        out[b] = o;
    }
}

// ---------------------------------------------------------------------------
extern "C" void kernel_launch(void* const* d_in, const int* in_sizes, int n_in,
                              void* d_out, int out_size) {
    (void)in_sizes; (void)n_in; (void)out_size;
    const float* x    = (const float*)d_in[0];
    const float* Wp   = (const float*)d_in[1];
    const float* bp   = (const float*)d_in[2];
    const float* prep = (const float*)d_in[3];
    const float* sig  = (const float*)d_in[4];
    const float* qff  = (const float*)d_in[5];
    const float* Wout = (const float*)d_in[6];
    const float* bout = (const float*)d_in[7];
    float* out = (float*)d_out;

    size_t smem = 131072 + 12288 + 10240 + 40 * 8 + 16 * 8 + 32 * 4;
    cudaFuncSetAttribute(qts_main, cudaFuncAttributeMaxDynamicSharedMemorySize, (int)smem);

    qts_proj<<<BATCH, 256>>>(x, Wp, bp, prep, sig, qff);
    qts_main<<<BATCH, 512, smem>>>(Wout, bout, out);
}